// round 15
// baseline (speedup 1.0000x reference)
#include <cuda_runtime.h>
#include <cuda_fp16.h>
#include <stdint.h>
#include <math.h>

#define BATCH  2
#define SEQ    2048
#define DIM    1024
#define HEADS  16
#define DHEAD  64
#define INNER  1024
#define MTOT   (BATCH*SEQ)
#define SSCALE 0.125f
#define LOG2E  1.4426950408889634f

// ---------------------------------------------------------------------------
// Device-global scratch (all hi-only)
// ---------------------------------------------------------------------------
__device__ __half g_xh[MTOT * DIM];
__device__ __half g_Ph[MTOT * INNER];
__device__ __half g_Oh[MTOT * INNER];
__device__ __half g_Wqh[INNER * DIM];   // w_qkv[:, :1024]^T hi
__device__ __half g_Woh[DIM * INNER];   // w_out^T hi

// ---------------------------------------------------------------------------
// PTX helpers
// ---------------------------------------------------------------------------
__device__ __forceinline__ uint32_t smem_u32(const void* p) {
    uint32_t a;
    asm("{ .reg .u64 t; cvta.to.shared.u64 t, %1; cvt.u32.u64 %0, t; }" : "=r"(a) : "l"(p));
    return a;
}

#define CP_ASYNC16(dst, src) \
    asm volatile("cp.async.cg.shared.global [%0], [%1], 16;" :: "r"(dst), "l"(src) : "memory")
#define CP_COMMIT() asm volatile("cp.async.commit_group;" ::: "memory")
#define CP_WAIT1()  asm volatile("cp.async.wait_group 1;"  ::: "memory")

#define LDSM4(r0, r1, r2, r3, a) \
    asm volatile("ldmatrix.sync.aligned.m8n8.x4.shared.b16 {%0,%1,%2,%3}, [%4];" \
        : "=r"(r0), "=r"(r1), "=r"(r2), "=r"(r3) : "r"(a))
#define LDSM4T(r0, r1, r2, r3, a) \
    asm volatile("ldmatrix.sync.aligned.m8n8.x4.trans.shared.b16 {%0,%1,%2,%3}, [%4];" \
        : "=r"(r0), "=r"(r1), "=r"(r2), "=r"(r3) : "r"(a))

#define MMA16816(d, a0, a1, a2, a3, b0, b1) \
    asm volatile("mma.sync.aligned.m16n8k16.row.col.f32.f16.f16.f32 " \
        "{%0,%1,%2,%3}, {%4,%5,%6,%7}, {%8,%9}, {%0,%1,%2,%3};" \
        : "+f"((d)[0]), "+f"((d)[1]), "+f"((d)[2]), "+f"((d)[3]) \
        : "r"(a0), "r"(a1), "r"(a2), "r"(a3), "r"(b0), "r"(b1))

// packed fp16 2^x (one MUFU op for two values)
__device__ __forceinline__ uint32_t ex2_f16x2(float t0, float t1) {
    __half2 h = __floats2half2_rn(t0, t1);
    uint32_t a = *reinterpret_cast<uint32_t*>(&h), d;
    asm("ex2.approx.f16x2 %0, %1;" : "=r"(d) : "r"(a));
    return d;
}

// ---------------------------------------------------------------------------
// fp32 -> fp16 convert (hi only)
// ---------------------------------------------------------------------------
__global__ __launch_bounds__(256) void convert_h_kernel(
    const float* __restrict__ in, __half* __restrict__ hi, int n4)
{
    int i = blockIdx.x * 256 + threadIdx.x;
    if (i >= n4) return;
    float4 v = ((const float4*)in)[i];
    ((__half2*)hi)[2 * i]     = __floats2half2_rn(v.x, v.y);
    ((__half2*)hi)[2 * i + 1] = __floats2half2_rn(v.z, v.w);
}

// ---------------------------------------------------------------------------
// Fused transpose (hi only): z=0 -> w_qkv (ld 3072), z=1 -> w_out (ld 1024)
// ---------------------------------------------------------------------------
__global__ __launch_bounds__(256) void transpose2_h_kernel(
    const float* __restrict__ src0, __half* __restrict__ dst0,
    const float* __restrict__ src1, __half* __restrict__ dst1)
{
    __shared__ float t[32][33];
    const float* src = blockIdx.z ? src1 : src0;
    __half* dh       = blockIdx.z ? dst1 : dst0;
    const int ld_src = blockIdx.z ? DIM : 3 * INNER;
    int bx = blockIdx.x * 32;
    int by = blockIdx.y * 32;
    int x = threadIdx.x, y0 = threadIdx.y;
#pragma unroll
    for (int i = 0; i < 32; i += 8)
        t[y0 + i][x] = src[(size_t)(by + y0 + i) * ld_src + bx + x];
    __syncthreads();
#pragma unroll
    for (int i = 0; i < 32; i += 8)
        dh[(size_t)(bx + y0 + i) * 1024 + by + x] = __float2half_rn(t[x][y0 + i]);
}

// ---------------------------------------------------------------------------
// Plain fp16 GEMM (f32 acc): C[M,N] = Ah[M,K] @ Bh^T  (Bh stored [N][K])
// BM=128, BN=128, BK=64, 256 thr (8 warps 4m x 2n). 2-stage cp.async,
// 2 CTAs/SM, rows padded to 72 halfs (144B, conflict-free ldmatrix).
// ---------------------------------------------------------------------------
#define G_TILE_B  18432                       // 128*72*2
#define G_STAGE_B (2 * G_TILE_B)              // 36864
#define G_SMEM_B  (2 * G_STAGE_B)             // 73728

__global__ __launch_bounds__(256, 2) void gemm_h_kernel(
    const __half* __restrict__ Ah, const __half* __restrict__ Bh,
    float* __restrict__ Cf, const float* __restrict__ bias,
    __half* __restrict__ Ch,
    int K, int ldc)
{
    extern __shared__ char smem[];
    const uint32_t sb = smem_u32(smem);
    const int tid = threadIdx.x;
    const int lane = tid & 31, wid = tid >> 5;
    const int g = lane >> 2, q = lane & 3;
    const int ml = lane >> 3, rl = lane & 7;
    const int wm = wid >> 1, wn = wid & 1;
    const int brow = blockIdx.y * 128;
    const int bcol = blockIdx.x * 128;

    float acc[2][8][4];
#pragma unroll
    for (int a = 0; a < 2; a++)
#pragma unroll
        for (int b = 0; b < 8; b++)
#pragma unroll
            for (int c = 0; c < 4; c++) acc[a][b][c] = 0.f;

#define G_LOAD(kt_, s_) do {                                                       \
    int _k0 = (kt_) << 6;                                                          \
    _Pragma("unroll")                                                              \
    for (int _i = 0; _i < 8; _i++) {                                               \
        int _id = tid + (_i << 8);                                                 \
        int _t = _id >> 10, _row = (_id >> 3) & 127, _c = _id & 7;                 \
        const __half* _src = _t ? Bh : Ah;                                         \
        int _grow = (_t ? bcol : brow) + _row;                                     \
        uint32_t _dst = sb + (s_) * G_STAGE_B + _t * G_TILE_B + _row * 144 + (_c << 4); \
        CP_ASYNC16(_dst, _src + (size_t)_grow * K + _k0 + (_c << 3));              \
    }                                                                              \
} while (0)

    G_LOAD(0, 0); CP_COMMIT();
    G_LOAD(1, 1); CP_COMMIT();

    const int nkt = K >> 6;   // 16 iterations for K=1024
    for (int kt = 0; kt < nkt; kt++) {
        CP_WAIT1();
        __syncthreads();
        const uint32_t base = sb + (kt & 1) * G_STAGE_B;

#pragma unroll
        for (int ks = 0; ks < 4; ks++) {
            const int kk = ks << 4;
            uint32_t ah[2][4];
#pragma unroll
            for (int mt = 0; mt < 2; mt++) {
                int arow = wm * 32 + mt * 16 + (ml & 1) * 8 + rl;
                int acol = kk + (ml >> 1) * 8;
                uint32_t off = (uint32_t)(arow * 72 + acol) * 2;
                LDSM4(ah[mt][0], ah[mt][1], ah[mt][2], ah[mt][3], base + off);
            }
#pragma unroll
            for (int nt2 = 0; nt2 < 4; nt2++) {
                int br = wn * 64 + nt2 * 16 + (ml >> 1) * 8 + rl;
                int bc = kk + (ml & 1) * 8;
                uint32_t off = (uint32_t)(br * 72 + bc) * 2;
                uint32_t bh0, bh1, bh2, bh3;
                LDSM4(bh0, bh1, bh2, bh3, base + G_TILE_B + off);
#pragma unroll
                for (int mt = 0; mt < 2; mt++) {
                    MMA16816(acc[mt][2 * nt2],     ah[mt][0], ah[mt][1], ah[mt][2], ah[mt][3], bh0, bh1);
                    MMA16816(acc[mt][2 * nt2 + 1], ah[mt][0], ah[mt][1], ah[mt][2], ah[mt][3], bh2, bh3);
                }
            }
        }
        __syncthreads();
        if (kt + 2 < nkt) G_LOAD(kt + 2, kt & 1);
        CP_COMMIT();
    }

#pragma unroll
    for (int mt = 0; mt < 2; mt++) {
#pragma unroll
        for (int nt = 0; nt < 8; nt++) {
            int row = brow + wm * 32 + mt * 16 + g;
            int col = bcol + wn * 64 + nt * 8 + 2 * q;
            float c0 = acc[mt][nt][0], c1 = acc[mt][nt][1];
            float c2 = acc[mt][nt][2], c3 = acc[mt][nt][3];
            if (Cf) {
                if (bias) { c0 += bias[col]; c1 += bias[col + 1]; c2 += bias[col]; c3 += bias[col + 1]; }
                float2 v0 = {c0, c1}, v1 = {c2, c3};
                *(float2*)&Cf[(size_t)row * ldc + col] = v0;
                *(float2*)&Cf[(size_t)(row + 8) * ldc + col] = v1;
            } else {
                *(__half2*)&Ch[(size_t)row * ldc + col]       = __floats2half2_rn(c0, c1);
                *(__half2*)&Ch[(size_t)(row + 8) * ldc + col] = __floats2half2_rn(c2, c3);
            }
        }
    }
#undef G_LOAD
}

// ---------------------------------------------------------------------------
// Causal flash attention. Change vs R14: l ones-MMAs are (a) split into 2
// independent accumulator chains per mt and (b) interleaved into the PV
// ks-loop so they never form an isolated serial dependency block.
// ---------------------------------------------------------------------------
#define A_QTILE_B 8192                       // 64*64*2
#define A_KTILE_B 8192
#define A_KOFF    A_QTILE_B                  // 8192
#define A_SMEM_B  (A_KOFF + 2 * A_KTILE_B)   // 24576

#define SWZ(row_, chunk_) ((uint32_t)((row_) * 128 + (((chunk_) ^ ((row_) & 7)) << 4)))

__global__ __launch_bounds__(64, 6) void attn_mma_kernel(
    const __half* __restrict__ Ph, __half* __restrict__ Oh)
{
    extern __shared__ char smem[];
    const uint32_t sb = smem_u32(smem);
    const int qt = (gridDim.x - 1) - blockIdx.x;   // heaviest first
    const int h = blockIdx.y, b = blockIdx.z;
    const int tid = threadIdx.x;
    const int lane = tid & 31, wid = tid >> 5;     // 2 warps
    const int g = lane >> 2, q = lane & 3;
    const int ml = lane >> 3, rl = lane & 7;

    const size_t pbase = (size_t)b * SEQ * INNER + h * DHEAD;
    const uint32_t ONES2 = 0x3C003C00u;            // half2(1.0, 1.0)

    // Q prologue: 64 rows * 8 chunks = 512 -> 8/thread
#pragma unroll
    for (int i = 0; i < 8; i++) {
        int id = tid + (i << 6);
        int row = (id >> 3) & 63, c = id & 7;
        const __half* gp = Ph + pbase + (size_t)(qt * 64 + row) * INNER + (c << 3);
        CP_ASYNC16(sb + SWZ(row, c), gp);
    }
    CP_COMMIT();

#define A_LOADK(kt_, s_) do {                                                      \
    _Pragma("unroll")                                                              \
    for (int _i = 0; _i < 8; _i++) {                                               \
        int _id = tid + (_i << 6);                                                 \
        int _row = (_id >> 3) & 63, _c = _id & 7;                                  \
        const __half* _gp = Ph + pbase + (size_t)((kt_) * 64 + _row) * INNER + (_c << 3); \
        CP_ASYNC16(sb + A_KOFF + (s_) * A_KTILE_B + SWZ(_row, _c), _gp);           \
    }                                                                              \
} while (0)

    const int ntiles = qt + 1;
    A_LOADK(qt, 0); CP_COMMIT();
    A_LOADK((ntiles > 1 ? qt - 1 : qt), 1); CP_COMMIT();

    float o[2][8][4];
#pragma unroll
    for (int mt = 0; mt < 2; mt++)
#pragma unroll
        for (int nt = 0; nt < 8; nt++)
#pragma unroll
            for (int e = 0; e < 4; e++) o[mt][nt][e] = 0.f;
    float mL[4];                 // frozen (max+2)*log2e per row-group
    float l_acc[2][2][4];        // [mt][chain] P @ ones accumulators
#pragma unroll
    for (int mt = 0; mt < 2; mt++)
#pragma unroll
        for (int c = 0; c < 2; c++)
#pragma unroll
            for (int e = 0; e < 4; e++) l_acc[mt][c][e] = 0.f;

    for (int t = 0; t < ntiles; t++) {
        CP_WAIT1();
        __syncthreads();
        const uint32_t kh_base = sb + A_KOFF + (t & 1) * A_KTILE_B;
        const bool diag = (t == 0);
        const int kbase = (qt - t) * 64;

        // ---- S = Qh·Kh^T ----
        float s[2][8][4];
#pragma unroll
        for (int mt = 0; mt < 2; mt++)
#pragma unroll
            for (int nt = 0; nt < 8; nt++)
#pragma unroll
                for (int e = 0; e < 4; e++) s[mt][nt][e] = 0.f;

#pragma unroll
        for (int ks = 0; ks < 4; ks++) {
            uint32_t qh[2][4];
#pragma unroll
            for (int mt = 0; mt < 2; mt++) {
                int qrow = wid * 32 + mt * 16 + (ml & 1) * 8 + rl;
                int chunk = ks * 2 + (ml >> 1);
                uint32_t off = SWZ(qrow, chunk);
                LDSM4(qh[mt][0], qh[mt][1], qh[mt][2], qh[mt][3], sb + off);
            }
#pragma unroll
            for (int nt2 = 0; nt2 < 4; nt2++) {
                int br = nt2 * 16 + (ml >> 1) * 8 + rl;
                int bc = ks * 2 + (ml & 1);
                uint32_t off = SWZ(br, bc);
                uint32_t bh0, bh1, bh2, bh3;
                LDSM4(bh0, bh1, bh2, bh3, kh_base + off);
#pragma unroll
                for (int mt = 0; mt < 2; mt++) {
                    MMA16816(s[mt][2 * nt2],     qh[mt][0], qh[mt][1], qh[mt][2], qh[mt][3], bh0, bh1);
                    MMA16816(s[mt][2 * nt2 + 1], qh[mt][0], qh[mt][1], qh[mt][2], qh[mt][3], bh2, bh3);
                }
            }
        }

        // ---- diag tile: mask + frozen max ----
        if (diag) {
#pragma unroll
            for (int mt = 0; mt < 2; mt++) {
#pragma unroll
                for (int half = 0; half < 2; half++) {
                    const int rr = mt * 2 + half;
                    const int qrow = qt * 64 + wid * 32 + mt * 16 + g + half * 8;
                    float mt_ = -1e30f;
#pragma unroll
                    for (int nt = 0; nt < 8; nt++)
#pragma unroll
                        for (int e = 0; e < 2; e++) {
                            float v = s[mt][nt][half * 2 + e] * SSCALE;
                            if (kbase + nt * 8 + 2 * q + e > qrow) v = -1e30f;
                            s[mt][nt][half * 2 + e] = v * LOG2E;
                            mt_ = fmaxf(mt_, v);
                        }
                    mt_ = fmaxf(mt_, __shfl_xor_sync(0xffffffffu, mt_, 1, 4));
                    mt_ = fmaxf(mt_, __shfl_xor_sync(0xffffffffu, mt_, 2, 4));
                    mL[rr] = (mt_ + 2.0f) * LOG2E;
                }
            }
        }

        // ---- probs: packed fp16 2^x directly into A fragments ----
        const float scl2e = SSCALE * LOG2E;
        uint32_t pa[2][4][4];
#pragma unroll
        for (int mt = 0; mt < 2; mt++) {
#pragma unroll
            for (int nt = 0; nt < 8; nt++) {
#pragma unroll
                for (int half = 0; half < 2; half++) {
                    const float mm = mL[mt * 2 + half];
                    float t0, t1;
                    if (diag) {
                        t0 = s[mt][nt][half * 2 + 0] - mm;
                        t1 = s[mt][nt][half * 2 + 1] - mm;
                    } else {
                        t0 = fmaf(s[mt][nt][half * 2 + 0], scl2e, -mm);
                        t1 = fmaf(s[mt][nt][half * 2 + 1], scl2e, -mm);
                    }
                    pa[mt][nt >> 1][(nt & 1) * 2 + half] = ex2_f16x2(t0, t1);
                }
            }
        }

        // ---- O += P·Vh with l-MMAs interleaved (2 indep chains per mt) ----
#pragma unroll
        for (int ks = 0; ks < 4; ks++) {
#pragma unroll
            for (int mt = 0; mt < 2; mt++)
                MMA16816(l_acc[mt][ks & 1], pa[mt][ks][0], pa[mt][ks][1],
                         pa[mt][ks][2], pa[mt][ks][3], ONES2, ONES2);
#pragma unroll
            for (int nt2 = 0; nt2 < 4; nt2++) {
                int vrow = ks * 16 + (ml & 1) * 8 + rl;
                int vchunk = nt2 * 2 + (ml >> 1);
                uint32_t off = SWZ(vrow, vchunk);
                uint32_t vh0, vh1, vh2, vh3;
                LDSM4T(vh0, vh1, vh2, vh3, kh_base + off);
#pragma unroll
                for (int mt = 0; mt < 2; mt++) {
                    MMA16816(o[mt][2 * nt2],     pa[mt][ks][0], pa[mt][ks][1], pa[mt][ks][2], pa[mt][ks][3], vh0, vh1);
                    MMA16816(o[mt][2 * nt2 + 1], pa[mt][ks][0], pa[mt][ks][1], pa[mt][ks][2], pa[mt][ks][3], vh2, vh3);
                }
            }
        }

        __syncthreads();
        if (t + 2 < ntiles) A_LOADK(qt - (t + 2), t & 1);
        CP_COMMIT();
    }

    // ---- normalize + store ----
#pragma unroll
    for (int mt = 0; mt < 2; mt++) {
#pragma unroll
        for (int half = 0; half < 2; half++) {
            const float inv = 1.f / (l_acc[mt][0][half * 2] + l_acc[mt][1][half * 2]);
            const size_t row = (size_t)b * SEQ + qt * 64 + wid * 32 + mt * 16 + g + half * 8;
#pragma unroll
            for (int nt = 0; nt < 8; nt++) {
                float v0 = o[mt][nt][half * 2 + 0] * inv;
                float v1 = o[mt][nt][half * 2 + 1] * inv;
                size_t idx = row * INNER + h * DHEAD + nt * 8 + 2 * q;
                *(__half2*)&Oh[idx] = __floats2half2_rn(v0, v1);
            }
        }
    }
#undef A_LOADK
}

// ---------------------------------------------------------------------------
extern "C" void kernel_launch(void* const* d_in, const int* in_sizes, int n_in,
                              void* d_out, int out_size)
{
    const float* x     = (const float*)d_in[0];
    const float* w_qkv = (const float*)d_in[1];
    const float* w_out = (const float*)d_in[2];
    const float* b_out = (const float*)d_in[3];
    float* out = (float*)d_out;

    __half *xh, *Ph, *Ohp, *Wqh, *Woh;
    cudaGetSymbolAddress((void**)&xh, g_xh);
    cudaGetSymbolAddress((void**)&Ph, g_Ph);
    cudaGetSymbolAddress((void**)&Ohp, g_Oh);
    cudaGetSymbolAddress((void**)&Wqh, g_Wqh);
    cudaGetSymbolAddress((void**)&Woh, g_Woh);

    static int configured = 0;
    if (!configured) {
        cudaFuncSetAttribute(gemm_h_kernel,
                             cudaFuncAttributeMaxDynamicSharedMemorySize, G_SMEM_B);
        cudaFuncSetAttribute(attn_mma_kernel,
                             cudaFuncAttributeMaxDynamicSharedMemorySize, A_SMEM_B);
        configured = 1;
    }

    convert_h_kernel<<<(MTOT * DIM / 4 + 255) / 256, 256>>>(x, xh, MTOT * DIM / 4);
    dim3 tblk(32, 8), tgrd(32, 32, 2);
    transpose2_h_kernel<<<tgrd, tblk>>>(w_qkv, Wqh, w_out, Woh);

    dim3 gblk(256), ggrd(INNER / 128, MTOT / 128);   // (8, 32)
    gemm_h_kernel<<<ggrd, gblk, G_SMEM_B>>>(xh, Wqh, nullptr, nullptr, Ph, DIM, INNER);

    dim3 ablk(64), agrd(SEQ / 64, HEADS, BATCH);     // 1024 CTAs
    attn_mma_kernel<<<agrd, ablk, A_SMEM_B>>>(Ph, Ohp);

    gemm_h_kernel<<<ggrd, gblk, G_SMEM_B>>>(Ohp, Woh, out, b_out, nullptr, INNER, DIM);
}

// round 16
// speedup vs baseline: 1.0588x; 1.0588x over previous
#include <cuda_runtime.h>
#include <cuda_fp16.h>
#include <stdint.h>
#include <math.h>

#define BATCH  2
#define SEQ    2048
#define DIM    1024
#define HEADS  16
#define DHEAD  64
#define INNER  1024
#define MTOT   (BATCH*SEQ)
#define SSCALE 0.125f
#define LOG2E  1.4426950408889634f

// ---------------------------------------------------------------------------
// Device-global scratch (all hi-only)
// ---------------------------------------------------------------------------
__device__ __half g_xh[MTOT * DIM];
__device__ __half g_Ph[MTOT * INNER];
__device__ __half g_Oh[MTOT * INNER];
__device__ __half g_Wqh[INNER * DIM];   // w_qkv[:, :1024]^T hi
__device__ __half g_Woh[DIM * INNER];   // w_out^T hi

// ---------------------------------------------------------------------------
// PTX helpers
// ---------------------------------------------------------------------------
__device__ __forceinline__ uint32_t smem_u32(const void* p) {
    uint32_t a;
    asm("{ .reg .u64 t; cvta.to.shared.u64 t, %1; cvt.u32.u64 %0, t; }" : "=r"(a) : "l"(p));
    return a;
}

#define CP_ASYNC16(dst, src) \
    asm volatile("cp.async.cg.shared.global [%0], [%1], 16;" :: "r"(dst), "l"(src) : "memory")
#define CP_COMMIT() asm volatile("cp.async.commit_group;" ::: "memory")
#define CP_WAIT1()  asm volatile("cp.async.wait_group 1;"  ::: "memory")

#define LDSM4(r0, r1, r2, r3, a) \
    asm volatile("ldmatrix.sync.aligned.m8n8.x4.shared.b16 {%0,%1,%2,%3}, [%4];" \
        : "=r"(r0), "=r"(r1), "=r"(r2), "=r"(r3) : "r"(a))
#define LDSM4T(r0, r1, r2, r3, a) \
    asm volatile("ldmatrix.sync.aligned.m8n8.x4.trans.shared.b16 {%0,%1,%2,%3}, [%4];" \
        : "=r"(r0), "=r"(r1), "=r"(r2), "=r"(r3) : "r"(a))

#define MMA16816(d, a0, a1, a2, a3, b0, b1) \
    asm volatile("mma.sync.aligned.m16n8k16.row.col.f32.f16.f16.f32 " \
        "{%0,%1,%2,%3}, {%4,%5,%6,%7}, {%8,%9}, {%0,%1,%2,%3};" \
        : "+f"((d)[0]), "+f"((d)[1]), "+f"((d)[2]), "+f"((d)[3]) \
        : "r"(a0), "r"(a1), "r"(a2), "r"(a3), "r"(b0), "r"(b1))

// packed fp16 2^x (one MUFU op for two values)
__device__ __forceinline__ uint32_t ex2_f16x2(float t0, float t1) {
    __half2 h = __floats2half2_rn(t0, t1);
    uint32_t a = *reinterpret_cast<uint32_t*>(&h), d;
    asm("ex2.approx.f16x2 %0, %1;" : "=r"(d) : "r"(a));
    return d;
}

// ---------------------------------------------------------------------------
// fp32 -> fp16 convert (hi only)
// ---------------------------------------------------------------------------
__global__ __launch_bounds__(256) void convert_h_kernel(
    const float* __restrict__ in, __half* __restrict__ hi, int n4)
{
    int i = blockIdx.x * 256 + threadIdx.x;
    if (i >= n4) return;
    float4 v = ((const float4*)in)[i];
    ((__half2*)hi)[2 * i]     = __floats2half2_rn(v.x, v.y);
    ((__half2*)hi)[2 * i + 1] = __floats2half2_rn(v.z, v.w);
}

// ---------------------------------------------------------------------------
// Fused transpose (hi only): z=0 -> w_qkv (ld 3072), z=1 -> w_out (ld 1024)
// ---------------------------------------------------------------------------
__global__ __launch_bounds__(256) void transpose2_h_kernel(
    const float* __restrict__ src0, __half* __restrict__ dst0,
    const float* __restrict__ src1, __half* __restrict__ dst1)
{
    __shared__ float t[32][33];
    const float* src = blockIdx.z ? src1 : src0;
    __half* dh       = blockIdx.z ? dst1 : dst0;
    const int ld_src = blockIdx.z ? DIM : 3 * INNER;
    int bx = blockIdx.x * 32;
    int by = blockIdx.y * 32;
    int x = threadIdx.x, y0 = threadIdx.y;
#pragma unroll
    for (int i = 0; i < 32; i += 8)
        t[y0 + i][x] = src[(size_t)(by + y0 + i) * ld_src + bx + x];
    __syncthreads();
#pragma unroll
    for (int i = 0; i < 32; i += 8)
        dh[(size_t)(bx + y0 + i) * 1024 + by + x] = __float2half_rn(t[x][y0 + i]);
}

// ---------------------------------------------------------------------------
// Plain fp16 GEMM (f32 acc): C[M,N] = Ah[M,K] @ Bh^T  (Bh stored [N][K])
// BM=128, BN=128, BK=64, 256 thr (8 warps 4m x 2n). 2-stage cp.async,
// 2 CTAs/SM, rows padded to 72 halfs (144B, conflict-free ldmatrix).
// ---------------------------------------------------------------------------
#define G_TILE_B  18432                       // 128*72*2
#define G_STAGE_B (2 * G_TILE_B)              // 36864
#define G_SMEM_B  (2 * G_STAGE_B)             // 73728

__global__ __launch_bounds__(256, 2) void gemm_h_kernel(
    const __half* __restrict__ Ah, const __half* __restrict__ Bh,
    float* __restrict__ Cf, const float* __restrict__ bias,
    __half* __restrict__ Ch,
    int K, int ldc)
{
    extern __shared__ char smem[];
    const uint32_t sb = smem_u32(smem);
    const int tid = threadIdx.x;
    const int lane = tid & 31, wid = tid >> 5;
    const int g = lane >> 2, q = lane & 3;
    const int ml = lane >> 3, rl = lane & 7;
    const int wm = wid >> 1, wn = wid & 1;
    const int brow = blockIdx.y * 128;
    const int bcol = blockIdx.x * 128;

    float acc[2][8][4];
#pragma unroll
    for (int a = 0; a < 2; a++)
#pragma unroll
        for (int b = 0; b < 8; b++)
#pragma unroll
            for (int c = 0; c < 4; c++) acc[a][b][c] = 0.f;

#define G_LOAD(kt_, s_) do {                                                       \
    int _k0 = (kt_) << 6;                                                          \
    _Pragma("unroll")                                                              \
    for (int _i = 0; _i < 8; _i++) {                                               \
        int _id = tid + (_i << 8);                                                 \
        int _t = _id >> 10, _row = (_id >> 3) & 127, _c = _id & 7;                 \
        const __half* _src = _t ? Bh : Ah;                                         \
        int _grow = (_t ? bcol : brow) + _row;                                     \
        uint32_t _dst = sb + (s_) * G_STAGE_B + _t * G_TILE_B + _row * 144 + (_c << 4); \
        CP_ASYNC16(_dst, _src + (size_t)_grow * K + _k0 + (_c << 3));              \
    }                                                                              \
} while (0)

    G_LOAD(0, 0); CP_COMMIT();
    G_LOAD(1, 1); CP_COMMIT();

    const int nkt = K >> 6;   // 16 iterations for K=1024
    for (int kt = 0; kt < nkt; kt++) {
        CP_WAIT1();
        __syncthreads();
        const uint32_t base = sb + (kt & 1) * G_STAGE_B;

#pragma unroll
        for (int ks = 0; ks < 4; ks++) {
            const int kk = ks << 4;
            uint32_t ah[2][4];
#pragma unroll
            for (int mt = 0; mt < 2; mt++) {
                int arow = wm * 32 + mt * 16 + (ml & 1) * 8 + rl;
                int acol = kk + (ml >> 1) * 8;
                uint32_t off = (uint32_t)(arow * 72 + acol) * 2;
                LDSM4(ah[mt][0], ah[mt][1], ah[mt][2], ah[mt][3], base + off);
            }
#pragma unroll
            for (int nt2 = 0; nt2 < 4; nt2++) {
                int br = wn * 64 + nt2 * 16 + (ml >> 1) * 8 + rl;
                int bc = kk + (ml & 1) * 8;
                uint32_t off = (uint32_t)(br * 72 + bc) * 2;
                uint32_t bh0, bh1, bh2, bh3;
                LDSM4(bh0, bh1, bh2, bh3, base + G_TILE_B + off);
#pragma unroll
                for (int mt = 0; mt < 2; mt++) {
                    MMA16816(acc[mt][2 * nt2],     ah[mt][0], ah[mt][1], ah[mt][2], ah[mt][3], bh0, bh1);
                    MMA16816(acc[mt][2 * nt2 + 1], ah[mt][0], ah[mt][1], ah[mt][2], ah[mt][3], bh2, bh3);
                }
            }
        }
        __syncthreads();
        if (kt + 2 < nkt) G_LOAD(kt + 2, kt & 1);
        CP_COMMIT();
    }

#pragma unroll
    for (int mt = 0; mt < 2; mt++) {
#pragma unroll
        for (int nt = 0; nt < 8; nt++) {
            int row = brow + wm * 32 + mt * 16 + g;
            int col = bcol + wn * 64 + nt * 8 + 2 * q;
            float c0 = acc[mt][nt][0], c1 = acc[mt][nt][1];
            float c2 = acc[mt][nt][2], c3 = acc[mt][nt][3];
            if (Cf) {
                if (bias) { c0 += bias[col]; c1 += bias[col + 1]; c2 += bias[col]; c3 += bias[col + 1]; }
                float2 v0 = {c0, c1}, v1 = {c2, c3};
                *(float2*)&Cf[(size_t)row * ldc + col] = v0;
                *(float2*)&Cf[(size_t)(row + 8) * ldc + col] = v1;
            } else {
                *(__half2*)&Ch[(size_t)row * ldc + col]       = __floats2half2_rn(c0, c1);
                *(__half2*)&Ch[(size_t)(row + 8) * ldc + col] = __floats2half2_rn(c2, c3);
            }
        }
    }
#undef G_LOAD
}

// ---------------------------------------------------------------------------
// Causal flash attention (R14 configuration — measured local optimum).
// Diagonal-first frozen-max softmax; probs via ex2.approx.f16x2; l via
// a single contiguous block of P@ones MMAs per tile (ptxas schedules best).
// 64 q-rows/CTA, 2 warps x 32 q-rows, 64 threads, (64,6): no spills.
// ---------------------------------------------------------------------------
#define A_QTILE_B 8192                       // 64*64*2
#define A_KTILE_B 8192
#define A_KOFF    A_QTILE_B                  // 8192
#define A_SMEM_B  (A_KOFF + 2 * A_KTILE_B)   // 24576

#define SWZ(row_, chunk_) ((uint32_t)((row_) * 128 + (((chunk_) ^ ((row_) & 7)) << 4)))

__global__ __launch_bounds__(64, 6) void attn_mma_kernel(
    const __half* __restrict__ Ph, __half* __restrict__ Oh)
{
    extern __shared__ char smem[];
    const uint32_t sb = smem_u32(smem);
    const int qt = (gridDim.x - 1) - blockIdx.x;   // heaviest first
    const int h = blockIdx.y, b = blockIdx.z;
    const int tid = threadIdx.x;
    const int lane = tid & 31, wid = tid >> 5;     // 2 warps
    const int g = lane >> 2, q = lane & 3;
    const int ml = lane >> 3, rl = lane & 7;

    const size_t pbase = (size_t)b * SEQ * INNER + h * DHEAD;
    const uint32_t ONES2 = 0x3C003C00u;            // half2(1.0, 1.0)

    // Q prologue: 64 rows * 8 chunks = 512 -> 8/thread
#pragma unroll
    for (int i = 0; i < 8; i++) {
        int id = tid + (i << 6);
        int row = (id >> 3) & 63, c = id & 7;
        const __half* gp = Ph + pbase + (size_t)(qt * 64 + row) * INNER + (c << 3);
        CP_ASYNC16(sb + SWZ(row, c), gp);
    }
    CP_COMMIT();

#define A_LOADK(kt_, s_) do {                                                      \
    _Pragma("unroll")                                                              \
    for (int _i = 0; _i < 8; _i++) {                                               \
        int _id = tid + (_i << 6);                                                 \
        int _row = (_id >> 3) & 63, _c = _id & 7;                                  \
        const __half* _gp = Ph + pbase + (size_t)((kt_) * 64 + _row) * INNER + (_c << 3); \
        CP_ASYNC16(sb + A_KOFF + (s_) * A_KTILE_B + SWZ(_row, _c), _gp);           \
    }                                                                              \
} while (0)

    const int ntiles = qt + 1;
    A_LOADK(qt, 0); CP_COMMIT();
    A_LOADK((ntiles > 1 ? qt - 1 : qt), 1); CP_COMMIT();

    float o[2][8][4];
#pragma unroll
    for (int mt = 0; mt < 2; mt++)
#pragma unroll
        for (int nt = 0; nt < 8; nt++)
#pragma unroll
            for (int e = 0; e < 4; e++) o[mt][nt][e] = 0.f;
    float mL[4];                 // frozen (max+2)*log2e per row-group
    float l_acc[2][4];           // P @ ones accumulators
#pragma unroll
    for (int mt = 0; mt < 2; mt++)
#pragma unroll
        for (int e = 0; e < 4; e++) l_acc[mt][e] = 0.f;

    for (int t = 0; t < ntiles; t++) {
        CP_WAIT1();
        __syncthreads();
        const uint32_t kh_base = sb + A_KOFF + (t & 1) * A_KTILE_B;
        const bool diag = (t == 0);
        const int kbase = (qt - t) * 64;

        // ---- S = Qh·Kh^T ----
        float s[2][8][4];
#pragma unroll
        for (int mt = 0; mt < 2; mt++)
#pragma unroll
            for (int nt = 0; nt < 8; nt++)
#pragma unroll
                for (int e = 0; e < 4; e++) s[mt][nt][e] = 0.f;

#pragma unroll
        for (int ks = 0; ks < 4; ks++) {
            uint32_t qh[2][4];
#pragma unroll
            for (int mt = 0; mt < 2; mt++) {
                int qrow = wid * 32 + mt * 16 + (ml & 1) * 8 + rl;
                int chunk = ks * 2 + (ml >> 1);
                uint32_t off = SWZ(qrow, chunk);
                LDSM4(qh[mt][0], qh[mt][1], qh[mt][2], qh[mt][3], sb + off);
            }
#pragma unroll
            for (int nt2 = 0; nt2 < 4; nt2++) {
                int br = nt2 * 16 + (ml >> 1) * 8 + rl;
                int bc = ks * 2 + (ml & 1);
                uint32_t off = SWZ(br, bc);
                uint32_t bh0, bh1, bh2, bh3;
                LDSM4(bh0, bh1, bh2, bh3, kh_base + off);
#pragma unroll
                for (int mt = 0; mt < 2; mt++) {
                    MMA16816(s[mt][2 * nt2],     qh[mt][0], qh[mt][1], qh[mt][2], qh[mt][3], bh0, bh1);
                    MMA16816(s[mt][2 * nt2 + 1], qh[mt][0], qh[mt][1], qh[mt][2], qh[mt][3], bh2, bh3);
                }
            }
        }

        // ---- diag tile: mask + frozen max ----
        if (diag) {
#pragma unroll
            for (int mt = 0; mt < 2; mt++) {
#pragma unroll
                for (int half = 0; half < 2; half++) {
                    const int rr = mt * 2 + half;
                    const int qrow = qt * 64 + wid * 32 + mt * 16 + g + half * 8;
                    float mt_ = -1e30f;
#pragma unroll
                    for (int nt = 0; nt < 8; nt++)
#pragma unroll
                        for (int e = 0; e < 2; e++) {
                            float v = s[mt][nt][half * 2 + e] * SSCALE;
                            if (kbase + nt * 8 + 2 * q + e > qrow) v = -1e30f;
                            s[mt][nt][half * 2 + e] = v * LOG2E;
                            mt_ = fmaxf(mt_, v);
                        }
                    mt_ = fmaxf(mt_, __shfl_xor_sync(0xffffffffu, mt_, 1, 4));
                    mt_ = fmaxf(mt_, __shfl_xor_sync(0xffffffffu, mt_, 2, 4));
                    mL[rr] = (mt_ + 2.0f) * LOG2E;
                }
            }
        }

        // ---- probs: packed fp16 2^x directly into A fragments ----
        const float scl2e = SSCALE * LOG2E;
        uint32_t pa[2][4][4];
#pragma unroll
        for (int mt = 0; mt < 2; mt++) {
#pragma unroll
            for (int nt = 0; nt < 8; nt++) {
#pragma unroll
                for (int half = 0; half < 2; half++) {
                    const float mm = mL[mt * 2 + half];
                    float t0, t1;
                    if (diag) {
                        t0 = s[mt][nt][half * 2 + 0] - mm;
                        t1 = s[mt][nt][half * 2 + 1] - mm;
                    } else {
                        t0 = fmaf(s[mt][nt][half * 2 + 0], scl2e, -mm);
                        t1 = fmaf(s[mt][nt][half * 2 + 1], scl2e, -mm);
                    }
                    pa[mt][nt >> 1][(nt & 1) * 2 + half] = ex2_f16x2(t0, t1);
                }
            }
        }

        // ---- l += P @ ones ----
#pragma unroll
        for (int ks = 0; ks < 4; ks++)
#pragma unroll
            for (int mt = 0; mt < 2; mt++)
                MMA16816(l_acc[mt], pa[mt][ks][0], pa[mt][ks][1],
                         pa[mt][ks][2], pa[mt][ks][3], ONES2, ONES2);

        // ---- O += P·Vh ----
#pragma unroll
        for (int ks = 0; ks < 4; ks++) {
#pragma unroll
            for (int nt2 = 0; nt2 < 4; nt2++) {
                int vrow = ks * 16 + (ml & 1) * 8 + rl;
                int vchunk = nt2 * 2 + (ml >> 1);
                uint32_t off = SWZ(vrow, vchunk);
                uint32_t vh0, vh1, vh2, vh3;
                LDSM4T(vh0, vh1, vh2, vh3, kh_base + off);
#pragma unroll
                for (int mt = 0; mt < 2; mt++) {
                    MMA16816(o[mt][2 * nt2],     pa[mt][ks][0], pa[mt][ks][1], pa[mt][ks][2], pa[mt][ks][3], vh0, vh1);
                    MMA16816(o[mt][2 * nt2 + 1], pa[mt][ks][0], pa[mt][ks][1], pa[mt][ks][2], pa[mt][ks][3], vh2, vh3);
                }
            }
        }

        __syncthreads();
        if (t + 2 < ntiles) A_LOADK(qt - (t + 2), t & 1);
        CP_COMMIT();
    }

    // ---- normalize + store ----
#pragma unroll
    for (int mt = 0; mt < 2; mt++) {
#pragma unroll
        for (int half = 0; half < 2; half++) {
            const float inv = 1.f / l_acc[mt][half * 2];
            const size_t row = (size_t)b * SEQ + qt * 64 + wid * 32 + mt * 16 + g + half * 8;
#pragma unroll
            for (int nt = 0; nt < 8; nt++) {
                float v0 = o[mt][nt][half * 2 + 0] * inv;
                float v1 = o[mt][nt][half * 2 + 1] * inv;
                size_t idx = row * INNER + h * DHEAD + nt * 8 + 2 * q;
                *(__half2*)&Oh[idx] = __floats2half2_rn(v0, v1);
            }
        }
    }
#undef A_LOADK
}

// ---------------------------------------------------------------------------
extern "C" void kernel_launch(void* const* d_in, const int* in_sizes, int n_in,
                              void* d_out, int out_size)
{
    const float* x     = (const float*)d_in[0];
    const float* w_qkv = (const float*)d_in[1];
    const float* w_out = (const float*)d_in[2];
    const float* b_out = (const float*)d_in[3];
    float* out = (float*)d_out;

    __half *xh, *Ph, *Ohp, *Wqh, *Woh;
    cudaGetSymbolAddress((void**)&xh, g_xh);
    cudaGetSymbolAddress((void**)&Ph, g_Ph);
    cudaGetSymbolAddress((void**)&Ohp, g_Oh);
    cudaGetSymbolAddress((void**)&Wqh, g_Wqh);
    cudaGetSymbolAddress((void**)&Woh, g_Woh);

    static int configured = 0;
    if (!configured) {
        cudaFuncSetAttribute(gemm_h_kernel,
                             cudaFuncAttributeMaxDynamicSharedMemorySize, G_SMEM_B);
        cudaFuncSetAttribute(attn_mma_kernel,
                             cudaFuncAttributeMaxDynamicSharedMemorySize, A_SMEM_B);
        configured = 1;
    }

    convert_h_kernel<<<(MTOT * DIM / 4 + 255) / 256, 256>>>(x, xh, MTOT * DIM / 4);
    dim3 tblk(32, 8), tgrd(32, 32, 2);
    transpose2_h_kernel<<<tgrd, tblk>>>(w_qkv, Wqh, w_out, Woh);

    dim3 gblk(256), ggrd(INNER / 128, MTOT / 128);   // (8, 32)
    gemm_h_kernel<<<ggrd, gblk, G_SMEM_B>>>(xh, Wqh, nullptr, nullptr, Ph, DIM, INNER);

    dim3 ablk(64), agrd(SEQ / 64, HEADS, BATCH);     // 1024 CTAs
    attn_mma_kernel<<<agrd, ablk, A_SMEM_B>>>(Ph, Ohp);

    gemm_h_kernel<<<ggrd, gblk, G_SMEM_B>>>(Ohp, Woh, out, b_out, nullptr, INNER, DIM);
}

// round 17
// speedup vs baseline: 1.1233x; 1.0609x over previous
#include <cuda_runtime.h>
#include <cuda_fp16.h>
#include <stdint.h>
#include <math.h>

#define BATCH  2
#define SEQ    2048
#define DIM    1024
#define HEADS  16
#define DHEAD  64
#define INNER  1024
#define MTOT   (BATCH*SEQ)
#define SSCALE 0.125f
#define LOG2E  1.4426950408889634f

// ---------------------------------------------------------------------------
// Device-global scratch (all hi-only)
// ---------------------------------------------------------------------------
__device__ __half g_xh[MTOT * DIM];
__device__ __half g_Ph[MTOT * INNER];
__device__ __half g_Oh[MTOT * INNER];
__device__ __half g_Wqh[INNER * DIM];   // w_qkv[:, :1024]^T hi
__device__ __half g_Woh[DIM * INNER];   // w_out^T hi

// ---------------------------------------------------------------------------
// PTX helpers
// ---------------------------------------------------------------------------
__device__ __forceinline__ uint32_t smem_u32(const void* p) {
    uint32_t a;
    asm("{ .reg .u64 t; cvta.to.shared.u64 t, %1; cvt.u32.u64 %0, t; }" : "=r"(a) : "l"(p));
    return a;
}

#define CP_ASYNC16(dst, src) \
    asm volatile("cp.async.cg.shared.global [%0], [%1], 16;" :: "r"(dst), "l"(src) : "memory")
#define CP_COMMIT() asm volatile("cp.async.commit_group;" ::: "memory")
#define CP_WAIT1()  asm volatile("cp.async.wait_group 1;"  ::: "memory")

#define LDSM4(r0, r1, r2, r3, a) \
    asm volatile("ldmatrix.sync.aligned.m8n8.x4.shared.b16 {%0,%1,%2,%3}, [%4];" \
        : "=r"(r0), "=r"(r1), "=r"(r2), "=r"(r3) : "r"(a))
#define LDSM4T(r0, r1, r2, r3, a) \
    asm volatile("ldmatrix.sync.aligned.m8n8.x4.trans.shared.b16 {%0,%1,%2,%3}, [%4];" \
        : "=r"(r0), "=r"(r1), "=r"(r2), "=r"(r3) : "r"(a))

#define MMA16816(d, a0, a1, a2, a3, b0, b1) \
    asm volatile("mma.sync.aligned.m16n8k16.row.col.f32.f16.f16.f32 " \
        "{%0,%1,%2,%3}, {%4,%5,%6,%7}, {%8,%9}, {%0,%1,%2,%3};" \
        : "+f"((d)[0]), "+f"((d)[1]), "+f"((d)[2]), "+f"((d)[3]) \
        : "r"(a0), "r"(a1), "r"(a2), "r"(a3), "r"(b0), "r"(b1))

// packed fp16 2^x (one MUFU op for two values)
__device__ __forceinline__ uint32_t ex2_f16x2(float t0, float t1) {
    __half2 h = __floats2half2_rn(t0, t1);
    uint32_t a = *reinterpret_cast<uint32_t*>(&h), d;
    asm("ex2.approx.f16x2 %0, %1;" : "=r"(d) : "r"(a));
    return d;
}

// ---------------------------------------------------------------------------
// fp32 -> fp16 convert (hi only)
// ---------------------------------------------------------------------------
__global__ __launch_bounds__(256) void convert_h_kernel(
    const float* __restrict__ in, __half* __restrict__ hi, int n4)
{
    int i = blockIdx.x * 256 + threadIdx.x;
    if (i >= n4) return;
    float4 v = ((const float4*)in)[i];
    ((__half2*)hi)[2 * i]     = __floats2half2_rn(v.x, v.y);
    ((__half2*)hi)[2 * i + 1] = __floats2half2_rn(v.z, v.w);
}

// ---------------------------------------------------------------------------
// Fused transpose (hi only): z=0 -> w_qkv (ld 3072), z=1 -> w_out (ld 1024)
// ---------------------------------------------------------------------------
__global__ __launch_bounds__(256) void transpose2_h_kernel(
    const float* __restrict__ src0, __half* __restrict__ dst0,
    const float* __restrict__ src1, __half* __restrict__ dst1)
{
    __shared__ float t[32][33];
    const float* src = blockIdx.z ? src1 : src0;
    __half* dh       = blockIdx.z ? dst1 : dst0;
    const int ld_src = blockIdx.z ? DIM : 3 * INNER;
    int bx = blockIdx.x * 32;
    int by = blockIdx.y * 32;
    int x = threadIdx.x, y0 = threadIdx.y;
#pragma unroll
    for (int i = 0; i < 32; i += 8)
        t[y0 + i][x] = src[(size_t)(by + y0 + i) * ld_src + bx + x];
    __syncthreads();
#pragma unroll
    for (int i = 0; i < 32; i += 8)
        dh[(size_t)(bx + y0 + i) * 1024 + by + x] = __float2half_rn(t[x][y0 + i]);
}

// ---------------------------------------------------------------------------
// Plain fp16 GEMM (f32 acc): C[M,N] = Ah[M,K] @ Bh^T  (Bh stored [N][K])
// BM=128, BN=128, BK=64, 256 thr (8 warps 4m x 2n). 2-stage cp.async,
// 2 CTAs/SM, rows padded to 72 halfs (144B, conflict-free ldmatrix).
// ---------------------------------------------------------------------------
#define G_TILE_B  18432                       // 128*72*2
#define G_STAGE_B (2 * G_TILE_B)              // 36864
#define G_SMEM_B  (2 * G_STAGE_B)             // 73728

__global__ __launch_bounds__(256, 2) void gemm_h_kernel(
    const __half* __restrict__ Ah, const __half* __restrict__ Bh,
    float* __restrict__ Cf, const float* __restrict__ bias,
    __half* __restrict__ Ch,
    int K, int ldc)
{
    extern __shared__ char smem[];
    const uint32_t sb = smem_u32(smem);
    const int tid = threadIdx.x;
    const int lane = tid & 31, wid = tid >> 5;
    const int g = lane >> 2, q = lane & 3;
    const int ml = lane >> 3, rl = lane & 7;
    const int wm = wid >> 1, wn = wid & 1;
    const int brow = blockIdx.y * 128;
    const int bcol = blockIdx.x * 128;

    float acc[2][8][4];
#pragma unroll
    for (int a = 0; a < 2; a++)
#pragma unroll
        for (int b = 0; b < 8; b++)
#pragma unroll
            for (int c = 0; c < 4; c++) acc[a][b][c] = 0.f;

#define G_LOAD(kt_, s_) do {                                                       \
    int _k0 = (kt_) << 6;                                                          \
    _Pragma("unroll")                                                              \
    for (int _i = 0; _i < 8; _i++) {                                               \
        int _id = tid + (_i << 8);                                                 \
        int _t = _id >> 10, _row = (_id >> 3) & 127, _c = _id & 7;                 \
        const __half* _src = _t ? Bh : Ah;                                         \
        int _grow = (_t ? bcol : brow) + _row;                                     \
        uint32_t _dst = sb + (s_) * G_STAGE_B + _t * G_TILE_B + _row * 144 + (_c << 4); \
        CP_ASYNC16(_dst, _src + (size_t)_grow * K + _k0 + (_c << 3));              \
    }                                                                              \
} while (0)

    G_LOAD(0, 0); CP_COMMIT();
    G_LOAD(1, 1); CP_COMMIT();

    const int nkt = K >> 6;   // 16 iterations for K=1024
    for (int kt = 0; kt < nkt; kt++) {
        CP_WAIT1();
        __syncthreads();
        const uint32_t base = sb + (kt & 1) * G_STAGE_B;

#pragma unroll
        for (int ks = 0; ks < 4; ks++) {
            const int kk = ks << 4;
            uint32_t ah[2][4];
#pragma unroll
            for (int mt = 0; mt < 2; mt++) {
                int arow = wm * 32 + mt * 16 + (ml & 1) * 8 + rl;
                int acol = kk + (ml >> 1) * 8;
                uint32_t off = (uint32_t)(arow * 72 + acol) * 2;
                LDSM4(ah[mt][0], ah[mt][1], ah[mt][2], ah[mt][3], base + off);
            }
#pragma unroll
            for (int nt2 = 0; nt2 < 4; nt2++) {
                int br = wn * 64 + nt2 * 16 + (ml >> 1) * 8 + rl;
                int bc = kk + (ml & 1) * 8;
                uint32_t off = (uint32_t)(br * 72 + bc) * 2;
                uint32_t bh0, bh1, bh2, bh3;
                LDSM4(bh0, bh1, bh2, bh3, base + G_TILE_B + off);
#pragma unroll
                for (int mt = 0; mt < 2; mt++) {
                    MMA16816(acc[mt][2 * nt2],     ah[mt][0], ah[mt][1], ah[mt][2], ah[mt][3], bh0, bh1);
                    MMA16816(acc[mt][2 * nt2 + 1], ah[mt][0], ah[mt][1], ah[mt][2], ah[mt][3], bh2, bh3);
                }
            }
        }
        __syncthreads();
        if (kt + 2 < nkt) G_LOAD(kt + 2, kt & 1);
        CP_COMMIT();
    }

#pragma unroll
    for (int mt = 0; mt < 2; mt++) {
#pragma unroll
        for (int nt = 0; nt < 8; nt++) {
            int row = brow + wm * 32 + mt * 16 + g;
            int col = bcol + wn * 64 + nt * 8 + 2 * q;
            float c0 = acc[mt][nt][0], c1 = acc[mt][nt][1];
            float c2 = acc[mt][nt][2], c3 = acc[mt][nt][3];
            if (Cf) {
                if (bias) { c0 += bias[col]; c1 += bias[col + 1]; c2 += bias[col]; c3 += bias[col + 1]; }
                float2 v0 = {c0, c1}, v1 = {c2, c3};
                *(float2*)&Cf[(size_t)row * ldc + col] = v0;
                *(float2*)&Cf[(size_t)(row + 8) * ldc + col] = v1;
            } else {
                *(__half2*)&Ch[(size_t)row * ldc + col]       = __floats2half2_rn(c0, c1);
                *(__half2*)&Ch[(size_t)(row + 8) * ldc + col] = __floats2half2_rn(c2, c3);
            }
        }
    }
#undef G_LOAD
}

// ---------------------------------------------------------------------------
// Causal flash attention — TRIANGLE-PAIRED: each CTA sequentially processes
// q-blocks {31-bx, bx} => exactly 33 tiles per CTA, 512 equal CTAs, single
// wave, no solo-CTA endgame. Per-pass body identical to the R16 optimum.
// 64 q-rows/pass, 2 warps x 32 q-rows, 64 threads, (64,6): no spills.
// ---------------------------------------------------------------------------
#define A_QTILE_B 8192                       // 64*64*2
#define A_KTILE_B 8192
#define A_KOFF    A_QTILE_B                  // 8192
#define A_SMEM_B  (A_KOFF + 2 * A_KTILE_B)   // 24576

#define SWZ(row_, chunk_) ((uint32_t)((row_) * 128 + (((chunk_) ^ ((row_) & 7)) << 4)))

__global__ __launch_bounds__(64, 6) void attn_mma_kernel(
    const __half* __restrict__ Ph, __half* __restrict__ Oh)
{
    extern __shared__ char smem[];
    const uint32_t sb = smem_u32(smem);
    const int nqt = gridDim.x * 2;                 // 32 q-blocks
    const int h = blockIdx.y, b = blockIdx.z;
    const int tid = threadIdx.x;
    const int lane = tid & 31, wid = tid >> 5;     // 2 warps
    const int g = lane >> 2, q = lane & 3;
    const int ml = lane >> 3, rl = lane & 7;

    const size_t pbase = (size_t)b * SEQ * INNER + h * DHEAD;
    const uint32_t ONES2 = 0x3C003C00u;            // half2(1.0, 1.0)

#define A_LOADK(kt_, s_) do {                                                      \
    _Pragma("unroll")                                                              \
    for (int _i = 0; _i < 8; _i++) {                                               \
        int _id = tid + (_i << 6);                                                 \
        int _row = (_id >> 3) & 63, _c = _id & 7;                                  \
        const __half* _gp = Ph + pbase + (size_t)((kt_) * 64 + _row) * INNER + (_c << 3); \
        CP_ASYNC16(sb + A_KOFF + (s_) * A_KTILE_B + SWZ(_row, _c), _gp);           \
    }                                                                              \
} while (0)

    for (int pass = 0; pass < 2; pass++) {
        const int qt = pass ? blockIdx.x : (nqt - 1 - blockIdx.x);

        // ---- Q prologue: 64 rows * 8 chunks = 512 -> 8/thread ----
#pragma unroll
        for (int i = 0; i < 8; i++) {
            int id = tid + (i << 6);
            int row = (id >> 3) & 63, c = id & 7;
            const __half* gp = Ph + pbase + (size_t)(qt * 64 + row) * INNER + (c << 3);
            CP_ASYNC16(sb + SWZ(row, c), gp);
        }
        CP_COMMIT();

        const int ntiles = qt + 1;
        A_LOADK(qt, 0); CP_COMMIT();
        A_LOADK((ntiles > 1 ? qt - 1 : qt), 1); CP_COMMIT();

        float o[2][8][4];
#pragma unroll
        for (int mt = 0; mt < 2; mt++)
#pragma unroll
            for (int nt = 0; nt < 8; nt++)
#pragma unroll
                for (int e = 0; e < 4; e++) o[mt][nt][e] = 0.f;
        float mL[4];                 // frozen (max+2)*log2e per row-group
        float l_acc[2][4];           // P @ ones accumulators
#pragma unroll
        for (int mt = 0; mt < 2; mt++)
#pragma unroll
            for (int e = 0; e < 4; e++) l_acc[mt][e] = 0.f;

        for (int t = 0; t < ntiles; t++) {
            CP_WAIT1();
            __syncthreads();
            const uint32_t kh_base = sb + A_KOFF + (t & 1) * A_KTILE_B;
            const bool diag = (t == 0);
            const int kbase = (qt - t) * 64;

            // ---- S = Qh·Kh^T ----
            float s[2][8][4];
#pragma unroll
            for (int mt = 0; mt < 2; mt++)
#pragma unroll
                for (int nt = 0; nt < 8; nt++)
#pragma unroll
                    for (int e = 0; e < 4; e++) s[mt][nt][e] = 0.f;

#pragma unroll
            for (int ks = 0; ks < 4; ks++) {
                uint32_t qh[2][4];
#pragma unroll
                for (int mt = 0; mt < 2; mt++) {
                    int qrow = wid * 32 + mt * 16 + (ml & 1) * 8 + rl;
                    int chunk = ks * 2 + (ml >> 1);
                    uint32_t off = SWZ(qrow, chunk);
                    LDSM4(qh[mt][0], qh[mt][1], qh[mt][2], qh[mt][3], sb + off);
                }
#pragma unroll
                for (int nt2 = 0; nt2 < 4; nt2++) {
                    int br = nt2 * 16 + (ml >> 1) * 8 + rl;
                    int bc = ks * 2 + (ml & 1);
                    uint32_t off = SWZ(br, bc);
                    uint32_t bh0, bh1, bh2, bh3;
                    LDSM4(bh0, bh1, bh2, bh3, kh_base + off);
#pragma unroll
                    for (int mt = 0; mt < 2; mt++) {
                        MMA16816(s[mt][2 * nt2],     qh[mt][0], qh[mt][1], qh[mt][2], qh[mt][3], bh0, bh1);
                        MMA16816(s[mt][2 * nt2 + 1], qh[mt][0], qh[mt][1], qh[mt][2], qh[mt][3], bh2, bh3);
                    }
                }
            }

            // ---- diag tile: mask + frozen max ----
            if (diag) {
#pragma unroll
                for (int mt = 0; mt < 2; mt++) {
#pragma unroll
                    for (int half = 0; half < 2; half++) {
                        const int rr = mt * 2 + half;
                        const int qrow = qt * 64 + wid * 32 + mt * 16 + g + half * 8;
                        float mt_ = -1e30f;
#pragma unroll
                        for (int nt = 0; nt < 8; nt++)
#pragma unroll
                            for (int e = 0; e < 2; e++) {
                                float v = s[mt][nt][half * 2 + e] * SSCALE;
                                if (kbase + nt * 8 + 2 * q + e > qrow) v = -1e30f;
                                s[mt][nt][half * 2 + e] = v * LOG2E;
                                mt_ = fmaxf(mt_, v);
                            }
                        mt_ = fmaxf(mt_, __shfl_xor_sync(0xffffffffu, mt_, 1, 4));
                        mt_ = fmaxf(mt_, __shfl_xor_sync(0xffffffffu, mt_, 2, 4));
                        mL[rr] = (mt_ + 2.0f) * LOG2E;
                    }
                }
            }

            // ---- probs: packed fp16 2^x directly into A fragments ----
            const float scl2e = SSCALE * LOG2E;
            uint32_t pa[2][4][4];
#pragma unroll
            for (int mt = 0; mt < 2; mt++) {
#pragma unroll
                for (int nt = 0; nt < 8; nt++) {
#pragma unroll
                    for (int half = 0; half < 2; half++) {
                        const float mm = mL[mt * 2 + half];
                        float t0, t1;
                        if (diag) {
                            t0 = s[mt][nt][half * 2 + 0] - mm;
                            t1 = s[mt][nt][half * 2 + 1] - mm;
                        } else {
                            t0 = fmaf(s[mt][nt][half * 2 + 0], scl2e, -mm);
                            t1 = fmaf(s[mt][nt][half * 2 + 1], scl2e, -mm);
                        }
                        pa[mt][nt >> 1][(nt & 1) * 2 + half] = ex2_f16x2(t0, t1);
                    }
                }
            }

            // ---- l += P @ ones ----
#pragma unroll
            for (int ks = 0; ks < 4; ks++)
#pragma unroll
                for (int mt = 0; mt < 2; mt++)
                    MMA16816(l_acc[mt], pa[mt][ks][0], pa[mt][ks][1],
                             pa[mt][ks][2], pa[mt][ks][3], ONES2, ONES2);

            // ---- O += P·Vh ----
#pragma unroll
            for (int ks = 0; ks < 4; ks++) {
#pragma unroll
                for (int nt2 = 0; nt2 < 4; nt2++) {
                    int vrow = ks * 16 + (ml & 1) * 8 + rl;
                    int vchunk = nt2 * 2 + (ml >> 1);
                    uint32_t off = SWZ(vrow, vchunk);
                    uint32_t vh0, vh1, vh2, vh3;
                    LDSM4T(vh0, vh1, vh2, vh3, kh_base + off);
#pragma unroll
                    for (int mt = 0; mt < 2; mt++) {
                        MMA16816(o[mt][2 * nt2],     pa[mt][ks][0], pa[mt][ks][1], pa[mt][ks][2], pa[mt][ks][3], vh0, vh1);
                        MMA16816(o[mt][2 * nt2 + 1], pa[mt][ks][0], pa[mt][ks][1], pa[mt][ks][2], pa[mt][ks][3], vh2, vh3);
                    }
                }
            }

            __syncthreads();
            if (t + 2 < ntiles) A_LOADK(qt - (t + 2), t & 1);
            CP_COMMIT();
        }

        // ---- normalize + store ----
#pragma unroll
        for (int mt = 0; mt < 2; mt++) {
#pragma unroll
            for (int half = 0; half < 2; half++) {
                const float inv = 1.f / l_acc[mt][half * 2];
                const size_t row = (size_t)b * SEQ + qt * 64 + wid * 32 + mt * 16 + g + half * 8;
#pragma unroll
                for (int nt = 0; nt < 8; nt++) {
                    float v0 = o[mt][nt][half * 2 + 0] * inv;
                    float v1 = o[mt][nt][half * 2 + 1] * inv;
                    size_t idx = row * INNER + h * DHEAD + nt * 8 + 2 * q;
                    *(__half2*)&Oh[idx] = __floats2half2_rn(v0, v1);
                }
            }
        }
        __syncthreads();   // smem safe for next pass's prologue
    }
#undef A_LOADK
}

// ---------------------------------------------------------------------------
extern "C" void kernel_launch(void* const* d_in, const int* in_sizes, int n_in,
                              void* d_out, int out_size)
{
    const float* x     = (const float*)d_in[0];
    const float* w_qkv = (const float*)d_in[1];
    const float* w_out = (const float*)d_in[2];
    const float* b_out = (const float*)d_in[3];
    float* out = (float*)d_out;

    __half *xh, *Ph, *Ohp, *Wqh, *Woh;
    cudaGetSymbolAddress((void**)&xh, g_xh);
    cudaGetSymbolAddress((void**)&Ph, g_Ph);
    cudaGetSymbolAddress((void**)&Ohp, g_Oh);
    cudaGetSymbolAddress((void**)&Wqh, g_Wqh);
    cudaGetSymbolAddress((void**)&Woh, g_Woh);

    static int configured = 0;
    if (!configured) {
        cudaFuncSetAttribute(gemm_h_kernel,
                             cudaFuncAttributeMaxDynamicSharedMemorySize, G_SMEM_B);
        cudaFuncSetAttribute(attn_mma_kernel,
                             cudaFuncAttributeMaxDynamicSharedMemorySize, A_SMEM_B);
        configured = 1;
    }

    convert_h_kernel<<<(MTOT * DIM / 4 + 255) / 256, 256>>>(x, xh, MTOT * DIM / 4);
    dim3 tblk(32, 8), tgrd(32, 32, 2);
    transpose2_h_kernel<<<tgrd, tblk>>>(w_qkv, Wqh, w_out, Woh);

    dim3 gblk(256), ggrd(INNER / 128, MTOT / 128);   // (8, 32)
    gemm_h_kernel<<<ggrd, gblk, G_SMEM_B>>>(xh, Wqh, nullptr, nullptr, Ph, DIM, INNER);

    dim3 ablk(64), agrd(SEQ / 128, HEADS, BATCH);    // (16, 16, 2) = 512 CTAs
    attn_mma_kernel<<<agrd, ablk, A_SMEM_B>>>(Ph, Ohp);

    gemm_h_kernel<<<ggrd, gblk, G_SMEM_B>>>(Ohp, Woh, out, b_out, nullptr, INNER, DIM);
}